// round 13
// baseline (speedup 1.0000x reference)
#include <cuda_runtime.h>
#include <cstdint>

#define kB 16
#define kH 8
#define kA 512
#define kC 359   /* A - int(A*0.3) */
#define kSPLIT 10 /* am0/fused overlap split point (batches) */

// ---------------------------------------------------------------------------
// Scratch (device globals)
// ---------------------------------------------------------------------------
__device__ float g_QpT[kB * kA * kA];      // (B, A, A)  QpT[b,i,j] (j contiguous)
__device__ float g_KpT[kB * kA * kA];      // (B, A, A)  KpT[b,n,j]
__device__ float g_am0[kB * kA * kA];      // (B, A, A)  am0[b,i,n] (scaled)
__device__ float g_Vp[kB * kA];
__device__ float g_out3[kB * kH * kA];     // [bh*512 + i]

// ---------------------------------------------------------------------------
// Threefry2x32 — device (mutation factors) + host (keys)
// ---------------------------------------------------------------------------
__device__ __forceinline__ void tf2x32(unsigned k0, unsigned k1,
                                       unsigned x0, unsigned x1,
                                       unsigned &o0, unsigned &o1) {
    unsigned ks2 = k0 ^ k1 ^ 0x1BD11BDAu;
    x0 += k0; x1 += k1;
#define TF_R(r) { x0 += x1; x1 = __funnelshift_l(x1, x1, r); x1 ^= x0; }
    TF_R(13) TF_R(15) TF_R(26) TF_R(6)
    x0 += k1;  x1 += ks2 + 1u;
    TF_R(17) TF_R(29) TF_R(16) TF_R(24)
    x0 += ks2; x1 += k0 + 2u;
    TF_R(13) TF_R(15) TF_R(26) TF_R(6)
    x0 += k0;  x1 += k1 + 3u;
    TF_R(17) TF_R(29) TF_R(16) TF_R(24)
    x0 += k1;  x1 += ks2 + 4u;
    TF_R(13) TF_R(15) TF_R(26) TF_R(6)
    x0 += ks2; x1 += k0 + 5u;
#undef TF_R
    o0 = x0; o1 = x1;
}
__device__ __forceinline__ float unit_float(unsigned bits) {
    return __uint_as_float((bits >> 9) | 0x3f800000u) - 1.0f;
}
__device__ __forceinline__ float mut_factor(unsigned bits) {
    const float mn = 0.7f, mx = 1.3f;
    return fmaxf(mn, unit_float(bits) * (mx - mn) + mn);
}
__device__ __forceinline__ float warpSum(float v) {
#pragma unroll
    for (int o = 16; o > 0; o >>= 1) v += __shfl_xor_sync(0xffffffffu, v, o);
    return v;
}

static inline unsigned h_rotl(unsigned v, int r) { return (v << r) | (v >> (32 - r)); }
static void h_tf2x32(unsigned k0, unsigned k1, unsigned x0, unsigned x1,
                     unsigned &o0, unsigned &o1) {
    unsigned ks2 = k0 ^ k1 ^ 0x1BD11BDAu;
    x0 += k0; x1 += k1;
#define TH_R(r) { x0 += x1; x1 = h_rotl(x1, r); x1 ^= x0; }
    TH_R(13) TH_R(15) TH_R(26) TH_R(6)
    x0 += k1;  x1 += ks2 + 1u;
    TH_R(17) TH_R(29) TH_R(16) TH_R(24)
    x0 += ks2; x1 += k0 + 2u;
    TH_R(13) TH_R(15) TH_R(26) TH_R(6)
    x0 += k0;  x1 += k1 + 3u;
    TH_R(17) TH_R(29) TH_R(16) TH_R(24)
    x0 += k1;  x1 += ks2 + 4u;
    TH_R(13) TH_R(15) TH_R(26) TH_R(6)
    x0 += ks2; x1 += k0 + 5u;
#undef TH_R
    o0 = x0; o1 = x1;
}
static inline float h_unit_float(unsigned bits) {
    union { unsigned u; float f; } c;
    c.u = (bits >> 9) | 0x3f800000u;
    return c.f - 1.0f;
}

// ---------------------------------------------------------------------------
// tf32 split-compensated NT GEMM, register-side hi/lo split.
// 128x128 tile, BK=8, 128 threads (4 warps, 64x64 warp tile), 2 CTA/SM.
// The 3 compensation terms are issued as 3 independent sweeps (hh, hl, lh)
// over all 32 accumulators — no back-to-back RAW on any accumulator.
// ---------------------------------------------------------------------------
__device__ __forceinline__ void mma_tf32(float c[4], const uint32_t a[4],
                                         uint32_t b0, uint32_t b1) {
    asm volatile(
        "mma.sync.aligned.m16n8k8.row.col.f32.tf32.tf32.f32 "
        "{%0,%1,%2,%3}, {%4,%5,%6,%7}, {%8,%9}, {%0,%1,%2,%3};\n"
        : "+f"(c[0]), "+f"(c[1]), "+f"(c[2]), "+f"(c[3])
        : "r"(a[0]), "r"(a[1]), "r"(a[2]), "r"(a[3]), "r"(b0), "r"(b1));
}
__device__ __forceinline__ void ldsm4(uint32_t r[4], uint32_t saddr) {
    asm volatile("ldmatrix.sync.aligned.m8n8.x4.shared.b16 {%0,%1,%2,%3}, [%4];"
                 : "=r"(r[0]), "=r"(r[1]), "=r"(r[2]), "=r"(r[3]) : "r"(saddr));
}
__device__ __forceinline__ int sw_off(int row, int kq) {
    return row * 8 + ((kq ^ ((row >> 2) & 1)) << 2);
}

template <bool OUT_T>
__global__ __launch_bounds__(128, 2)
void gemm_nt(const float* __restrict__ A0, const float* __restrict__ A1,
             const float* __restrict__ W0, const float* __restrict__ W1,
             const float* __restrict__ bias0, const float* __restrict__ bias1,
             float* __restrict__ C0, float* __restrict__ C1, float scale) {
    __shared__ float sA[2][1024], sB[2][1024];
    const int t = threadIdx.x;

    const float* A;
    const float* B;
    const float* bias;
    float* C;
    if (OUT_T) {
        const int sel = blockIdx.z;
        A = sel ? A1 : A0;
        B = sel ? W1 : W0;
        bias = sel ? bias1 : bias0;
        C = sel ? C1 : C0;
    } else {
        const int z = blockIdx.z;
        A = A0 + (size_t)z * (kA * kA);
        B = W0 + (size_t)z * (kA * kA);
        bias = nullptr;
        C = C0 + (size_t)z * (kA * kA);
    }
    const int n0 = blockIdx.x * 128;
    const int m0 = blockIdx.y * 128;

    const int lane = t & 31, wid = t >> 5;
    const int wm = (wid >> 1) * 64, wn = (wid & 1) * 64;
    const int gid = lane >> 2, tig = lane & 3;

    const float* Aptr = A + (size_t)(m0 + t) * 512;
    const float* Bptr = B + (size_t)(n0 + t) * 512;
    const int wOff0 = sw_off(t, 0), wOff1 = sw_off(t, 1);

    const int q = lane >> 3, rr = lane & 7;
    int aOff[4], bOff[4];
#pragma unroll
    for (int mi = 0; mi < 4; mi++) {
        int m = wm + mi * 16 + (q & 1) * 8 + rr;
        aOff[mi] = sw_off(m, q >> 1) * 4;
    }
#pragma unroll
    for (int p = 0; p < 4; p++) {
        int nrow = wn + (p * 2 + (q >> 1)) * 8 + rr;
        bOff[p] = sw_off(nrow, q & 1) * 4;
    }
    const uint32_t bA = (uint32_t)__cvta_generic_to_shared(&sA[0][0]);
    const uint32_t bB = (uint32_t)__cvta_generic_to_shared(&sB[0][0]);

    float c[4][8][4];
#pragma unroll
    for (int mi = 0; mi < 4; mi++)
#pragma unroll
        for (int ni = 0; ni < 8; ni++)
#pragma unroll
            for (int r = 0; r < 4; r++) c[mi][ni][r] = 0.f;

    float4 ra0, ra1, rb0, rb1;
    auto gload = [&](int k0) {
        ra0 = *reinterpret_cast<const float4*>(Aptr + k0);
        ra1 = *reinterpret_cast<const float4*>(Aptr + k0 + 4);
        rb0 = *reinterpret_cast<const float4*>(Bptr + k0);
        rb1 = *reinterpret_cast<const float4*>(Bptr + k0 + 4);
    };
    auto sts = [&](int buf) {
        *reinterpret_cast<float4*>(&sA[buf][wOff0]) = ra0;
        *reinterpret_cast<float4*>(&sA[buf][wOff1]) = ra1;
        *reinterpret_cast<float4*>(&sB[buf][wOff0]) = rb0;
        *reinterpret_cast<float4*>(&sB[buf][wOff1]) = rb1;
    };

    gload(0);
    sts(0);
    __syncthreads();

    for (int ks = 0; ks < 64; ks++) {
        const int buf = ks & 1;
        const uint32_t bo = (uint32_t)buf * 4096u;
        if (ks < 63) gload((ks + 1) * 8);

        uint32_t al[4][4], bl[4][4];     // raw load, becomes lo after split
        uint32_t ah[4][4], bh[4][4];
#pragma unroll
        for (int mi = 0; mi < 4; mi++) ldsm4(al[mi], bA + bo + aOff[mi]);
#pragma unroll
        for (int p = 0; p < 4; p++) ldsm4(bl[p], bB + bo + bOff[p]);

#pragma unroll
        for (int mi = 0; mi < 4; mi++)
#pragma unroll
            for (int r = 0; r < 4; r++) {
                uint32_t hv = al[mi][r] & 0xFFFFE000u;
                ah[mi][r] = hv;
                al[mi][r] = __float_as_uint(__uint_as_float(al[mi][r]) -
                                            __uint_as_float(hv));
            }
#pragma unroll
        for (int p = 0; p < 4; p++)
#pragma unroll
            for (int r = 0; r < 4; r++) {
                uint32_t hv = bl[p][r] & 0xFFFFE000u;
                bh[p][r] = hv;
                bl[p][r] = __float_as_uint(__uint_as_float(bl[p][r]) -
                                           __uint_as_float(hv));
            }

        // sweep 1: hh over all 32 accumulators (no RAW between consecutive mmas)
#pragma unroll
        for (int mi = 0; mi < 4; mi++)
#pragma unroll
            for (int ni = 0; ni < 8; ni++) {
                const int p = ni >> 1, s0 = (ni & 1) * 2;
                mma_tf32(c[mi][ni], ah[mi], bh[p][s0], bh[p][s0 + 1]);
            }
        // sweep 2: hi x lo
#pragma unroll
        for (int mi = 0; mi < 4; mi++)
#pragma unroll
            for (int ni = 0; ni < 8; ni++) {
                const int p = ni >> 1, s0 = (ni & 1) * 2;
                mma_tf32(c[mi][ni], ah[mi], bl[p][s0], bl[p][s0 + 1]);
            }
        // sweep 3: lo x hi
#pragma unroll
        for (int mi = 0; mi < 4; mi++)
#pragma unroll
            for (int ni = 0; ni < 8; ni++) {
                const int p = ni >> 1, s0 = (ni & 1) * 2;
                mma_tf32(c[mi][ni], al[mi], bh[p][s0], bh[p][s0 + 1]);
            }

        if (ks < 63) {
            sts(buf ^ 1);
            __syncthreads();
        }
    }

#pragma unroll
    for (int mi = 0; mi < 4; mi++) {
#pragma unroll
        for (int ni = 0; ni < 8; ni++) {
            const int gm = m0 + wm + mi * 16 + gid;
            const int gc = n0 + wn + ni * 8 + 2 * tig;
            if (OUT_T) {
                const float bv0 = bias[gc], bv1 = bias[gc + 1];
                float* Cb = C + (size_t)(gm >> 9) * (kA * kA);
                const int j0 = gm & 511, j1 = (gm + 8) & 511;
                Cb[(size_t)gc * 512 + j0]       = c[mi][ni][0] + bv0;
                Cb[(size_t)(gc + 1) * 512 + j0] = c[mi][ni][1] + bv1;
                Cb[(size_t)gc * 512 + j1]       = c[mi][ni][2] + bv0;
                Cb[(size_t)(gc + 1) * 512 + j1] = c[mi][ni][3] + bv1;
            } else {
                float2 o0, o1;
                o0.x = c[mi][ni][0] * scale; o0.y = c[mi][ni][1] * scale;
                o1.x = c[mi][ni][2] * scale; o1.y = c[mi][ni][3] * scale;
                *reinterpret_cast<float2*>(&C[(size_t)gm * 512 + gc]) = o0;
                *reinterpret_cast<float2*>(&C[(size_t)(gm + 8) * 512 + gc]) = o1;
            }
        }
    }
}

// ---------------------------------------------------------------------------
// Vp[b,i] = sum_k V[b,k]*Wv[i,k] + bv[i].  Block per i, warp w -> b=w,w+8.
// ---------------------------------------------------------------------------
__global__ __launch_bounds__(256)
void vp_kernel(const float* __restrict__ V, const float* __restrict__ Wv,
               const float* __restrict__ bv) {
    const int i = blockIdx.x;
    const int w = threadIdx.x >> 5, lane = threadIdx.x & 31;
    const float* wr = Wv + (size_t)i * 512;
    float a0 = 0.f, a1 = 0.f;
#pragma unroll
    for (int cc = 0; cc < 4; cc++) {
        const int k = cc * 128 + lane * 4;
        float4 w4 = *reinterpret_cast<const float4*>(wr + k);
        float4 v0 = *reinterpret_cast<const float4*>(V + w * 512 + k);
        float4 v1 = *reinterpret_cast<const float4*>(V + (w + 8) * 512 + k);
        a0 += w4.x * v0.x + w4.y * v0.y + w4.z * v0.z + w4.w * v0.w;
        a1 += w4.x * v1.x + w4.y * v1.y + w4.z * v1.z + w4.w * v1.w;
    }
    a0 = warpSum(a0); a1 = warpSum(a1);
    if (lane == 0) {
        float b = bv[i];
        g_Vp[w * 512 + i] = a0 + b;
        g_Vp[(w + 8) * 512 + i] = a1 + b;
    }
}

// ---------------------------------------------------------------------------
// Fused kernels — mutate / crossover chosen at capture time on host.
// b0 = batch offset (split-stream pipelining with am0 GEMM chunks).
// ---------------------------------------------------------------------------
__global__ __launch_bounds__(256)
void fused_mut(unsigned km0, unsigned km1, int b0) {
    const int i = blockIdx.x, b = blockIdx.y + b0;
    const int t = threadIdx.x, lane = t & 31, h = t >> 5;
    __shared__ float sv[512], svp[512];

    if (t < 128)
        *reinterpret_cast<float4*>(&sv[t * 4]) =
            *reinterpret_cast<const float4*>(g_am0 + ((size_t)b * kA + i) * kA + t * 4);
    else
        *reinterpret_cast<float4*>(&svp[(t - 128) * 4]) =
            *reinterpret_cast<const float4*>(g_Vp + b * kA + (t - 128) * 4);
    __syncthreads();

    const unsigned base = ((unsigned)(b * 8 + h) << 18) + ((unsigned)i << 9) + (unsigned)lane;
    float s = 0.f, d = 0.f;
#pragma unroll 8
    for (int cc = 0; cc < 16; cc++) {
        const int j = cc * 32 + lane;
        unsigned o0, o1;
        tf2x32(km0, km1, 0u, base + (unsigned)(cc * 32), o0, o1);
        const float e = __expf(sv[j] * mut_factor(o0 ^ o1));
        s += e; d += e * svp[j];
    }
    s = warpSum(s); d = warpSum(d);
    if (lane == 0) g_out3[(b * 8 + h) * kA + i] = d / s;
}

struct CrossArgs { int r1[kB * kH]; int r2[kB * kH]; };

__global__ __launch_bounds__(256)
void fused_cross(CrossArgs args, int b0) {
    const int i = blockIdx.x, b = blockIdx.y + b0;
    const int t = threadIdx.x, lane = t & 31, h = t >> 5;
    __shared__ float sv[512], svp[512];

    if (t < 128)
        *reinterpret_cast<float4*>(&sv[t * 4]) =
            *reinterpret_cast<const float4*>(g_am0 + ((size_t)b * kA + i) * kA + t * 4);
    else
        *reinterpret_cast<float4*>(&svp[(t - 128) * 4]) =
            *reinterpret_cast<const float4*>(g_Vp + b * kA + (t - 128) * 4);
    __syncthreads();

    const int bh = b * 8 + h;
    const int r1 = args.r1[bh], r2 = args.r2[bh];
    const int src = (i == r1) ? r2 : (i == r2) ? r1 : i;
    const float* srow = g_am0 + ((size_t)b * kA + src) * kA;
    float s = 0.f, d = 0.f;
#pragma unroll 4
    for (int cc = 0; cc < 16; cc++) {
        const int j = cc * 32 + lane;
        const float v = (src == i || j < kC) ? sv[j] : srow[j];
        const float e = __expf(v);
        s += e; d += e * svp[j];
    }
    s = warpSum(s); d = warpSum(d);
    if (lane == 0) g_out3[bh * kA + i] = d / s;
}

// ---------------------------------------------------------------------------
// y[b,o] = sum_x g_out3[b*4096+x]*WOw[o,x] + WOb[o].
// ---------------------------------------------------------------------------
__global__ __launch_bounds__(256)
void out_proj(const float* __restrict__ WOw, const float* __restrict__ WOb,
              float* __restrict__ y) {
    __shared__ float xs[16][516];
    const int t = threadIdx.x;
    const int o_l = t >> 4, bq = t & 15;
    const int o = blockIdx.x * 16 + o_l;
    float acc = 0.f;

    for (int ch = 0; ch < 8; ch++) {
#pragma unroll
        for (int l = 0; l < 8; l++) {
            int idx = t + l * 256;
            int row = idx >> 7, c4 = idx & 127;
            *reinterpret_cast<float4*>(&xs[row][c4 * 4]) =
                *reinterpret_cast<const float4*>(g_out3 + row * 4096 + ch * 512 + c4 * 4);
        }
        __syncthreads();
        const float4* Wp = reinterpret_cast<const float4*>(WOw + (size_t)o * 4096 + ch * 512);
#pragma unroll 8
        for (int k4 = 0; k4 < 128; k4++) {
            float4 w4 = Wp[k4];
            float4 x4 = *reinterpret_cast<const float4*>(&xs[bq][k4 * 4]);
            acc += w4.x * x4.x + w4.y * x4.y + w4.z * x4.z + w4.w * x4.w;
        }
        __syncthreads();
    }
    y[bq * 512 + o] = acc + WOb[o];
}

// ---------------------------------------------------------------------------
// Launch — host PRNG; two-stream overlap with asymmetric 10/6 am0 split:
//   s0: proj GEMM -> am0[0:10] -> am0[10:16] -> (wait fused) -> out_proj
//   s1: vp ......... (wait lo) fused[0:10]  (wait hi) fused[10:16]
// ---------------------------------------------------------------------------
extern "C" void kernel_launch(void* const* d_in, const int* in_sizes, int n_in,
                              void* d_out, int out_size) {
    const float* Q   = (const float*)d_in[0];
    const float* K   = (const float*)d_in[1];
    const float* V   = (const float*)d_in[2];
    const float* WQw = (const float*)d_in[3];
    const float* WQb = (const float*)d_in[4];
    const float* WKw = (const float*)d_in[5];
    const float* WKb = (const float*)d_in[6];
    const float* WVw = (const float*)d_in[7];
    const float* WVb = (const float*)d_in[8];
    const float* WOw = (const float*)d_in[9];
    const float* WOb = (const float*)d_in[10];
    float* y = (float*)d_out;

    float* dQpT; cudaGetSymbolAddress((void**)&dQpT, g_QpT);
    float* dKpT; cudaGetSymbolAddress((void**)&dKpT, g_KpT);
    float* dam;  cudaGetSymbolAddress((void**)&dam,  g_am0);

    static cudaStream_t s1 = nullptr;
    static cudaEvent_t evFork, evLo, evHi, evF;
    if (s1 == nullptr) {
        cudaStreamCreateWithFlags(&s1, cudaStreamNonBlocking);
        cudaEventCreateWithFlags(&evFork, cudaEventDisableTiming);
        cudaEventCreateWithFlags(&evLo,   cudaEventDisableTiming);
        cudaEventCreateWithFlags(&evHi,   cudaEventDisableTiming);
        cudaEventCreateWithFlags(&evF,    cudaEventDisableTiming);
    }

    // --- host PRNG (deterministic, key = 42) ---
    unsigned kp0, kp1, km0, km1, kr10, kr11, kr20, kr21;
    h_tf2x32(0u, 42u, 0u, 0u, kp0, kp1);
    h_tf2x32(0u, 42u, 0u, 1u, km0, km1);
    h_tf2x32(0u, 42u, 0u, 2u, kr10, kr11);
    h_tf2x32(0u, 42u, 0u, 3u, kr20, kr21);
    unsigned o0, o1;
    h_tf2x32(kp0, kp1, 0u, 0u, o0, o1);
    const bool mutate = (h_unit_float(o0 ^ o1) <= 0.6f);
    CrossArgs ca;
    if (!mutate) {
        unsigned a0, a1;
        h_tf2x32(kr10, kr11, 0u, 1u, a0, a1);
        for (int t = 0; t < kB * kH; t++) {
            h_tf2x32(a0, a1, 0u, (unsigned)t, o0, o1);
            ca.r1[t] = (int)((o0 ^ o1) & 511u);
        }
        h_tf2x32(kr20, kr21, 0u, 1u, a0, a1);
        for (int t = 0; t < kB * kH; t++) {
            h_tf2x32(a0, a1, 0u, (unsigned)t, o0, o1);
            ca.r2[t] = (int)((o0 ^ o1) & 511u);
        }
    }

    const size_t loOff = (size_t)kSPLIT * kA * kA;

    cudaEventRecord(evFork, 0);
    cudaStreamWaitEvent(s1, evFork, 0);

    // s1: Vp projection (overlaps the proj GEMM on s0)
    vp_kernel<<<512, 256, 0, s1>>>(V, WVw, WVb);

    // s0: merged Q/K projections
    gemm_nt<true><<<dim3(4, 64, 2), 128>>>(Q, K, WQw, WKw, WQb, WKb,
                                           dQpT, dKpT, 1.0f);
    // s0: am0 batches [0, kSPLIT) — 160 CTAs, fills the chip
    gemm_nt<false><<<dim3(4, 4, kSPLIT), 128>>>(dQpT, nullptr, dKpT, nullptr,
                                                nullptr, nullptr, dam, nullptr,
                                                1.0f / sqrtf(8.0f));
    cudaEventRecord(evLo, 0);
    // s0: am0 batches [kSPLIT, 16) — overlapped with fused_lo on s1
    gemm_nt<false><<<dim3(4, 4, kB - kSPLIT), 128>>>(dQpT + loOff, nullptr,
                                                     dKpT + loOff, nullptr,
                                                     nullptr, nullptr,
                                                     dam + loOff, nullptr,
                                                     1.0f / sqrtf(8.0f));
    cudaEventRecord(evHi, 0);

    cudaStreamWaitEvent(s1, evLo, 0);
    if (mutate)
        fused_mut<<<dim3(512, kSPLIT), 256, 0, s1>>>(km0, km1, 0);
    else
        fused_cross<<<dim3(512, kSPLIT), 256, 0, s1>>>(ca, 0);
    cudaStreamWaitEvent(s1, evHi, 0);
    if (mutate)
        fused_mut<<<dim3(512, kB - kSPLIT), 256, 0, s1>>>(km0, km1, kSPLIT);
    else
        fused_cross<<<dim3(512, kB - kSPLIT), 256, 0, s1>>>(ca, kSPLIT);
    cudaEventRecord(evF, s1);

    cudaStreamWaitEvent(0, evF, 0);
    out_proj<<<32, 256>>>(WOw, WOb, y);
}

// round 15
// speedup vs baseline: 1.0759x; 1.0759x over previous
#include <cuda_runtime.h>
#include <cuda_bf16.h>
#include <cstdint>

#define kB 16
#define kH 8
#define kA 512
#define kC 359   /* A - int(A*0.3) */

// ---------------------------------------------------------------------------
// Scratch (device globals)
// ---------------------------------------------------------------------------
__device__ float g_QpT[kB * kA * kA];      // (B, A, A)  QpT[b,i,j] (j contiguous)
__device__ float g_KpT[kB * kA * kA];      // (B, A, A)  KpT[b,n,j]
__device__ float g_am0[kB * kA * kA];      // (B, A, A)  am0[b,i,n] (scaled)
__device__ float g_Vp[kB * kA];
__device__ float g_out3[kB * kH * kA];     // [bh*512 + i]

// ---------------------------------------------------------------------------
// Threefry2x32 — device (mutation factors) + host (keys)
// ---------------------------------------------------------------------------
__device__ __forceinline__ void tf2x32(unsigned k0, unsigned k1,
                                       unsigned x0, unsigned x1,
                                       unsigned &o0, unsigned &o1) {
    unsigned ks2 = k0 ^ k1 ^ 0x1BD11BDAu;
    x0 += k0; x1 += k1;
#define TF_R(r) { x0 += x1; x1 = __funnelshift_l(x1, x1, r); x1 ^= x0; }
    TF_R(13) TF_R(15) TF_R(26) TF_R(6)
    x0 += k1;  x1 += ks2 + 1u;
    TF_R(17) TF_R(29) TF_R(16) TF_R(24)
    x0 += ks2; x1 += k0 + 2u;
    TF_R(13) TF_R(15) TF_R(26) TF_R(6)
    x0 += k0;  x1 += k1 + 3u;
    TF_R(17) TF_R(29) TF_R(16) TF_R(24)
    x0 += k1;  x1 += ks2 + 4u;
    TF_R(13) TF_R(15) TF_R(26) TF_R(6)
    x0 += ks2; x1 += k0 + 5u;
#undef TF_R
    o0 = x0; o1 = x1;
}
__device__ __forceinline__ float unit_float(unsigned bits) {
    return __uint_as_float((bits >> 9) | 0x3f800000u) - 1.0f;
}
__device__ __forceinline__ float mut_factor(unsigned bits) {
    const float mn = 0.7f, mx = 1.3f;
    return fmaxf(mn, unit_float(bits) * (mx - mn) + mn);
}
__device__ __forceinline__ float warpSum(float v) {
#pragma unroll
    for (int o = 16; o > 0; o >>= 1) v += __shfl_xor_sync(0xffffffffu, v, o);
    return v;
}

static inline unsigned h_rotl(unsigned v, int r) { return (v << r) | (v >> (32 - r)); }
static void h_tf2x32(unsigned k0, unsigned k1, unsigned x0, unsigned x1,
                     unsigned &o0, unsigned &o1) {
    unsigned ks2 = k0 ^ k1 ^ 0x1BD11BDAu;
    x0 += k0; x1 += k1;
#define TH_R(r) { x0 += x1; x1 = h_rotl(x1, r); x1 ^= x0; }
    TH_R(13) TH_R(15) TH_R(26) TH_R(6)
    x0 += k1;  x1 += ks2 + 1u;
    TH_R(17) TH_R(29) TH_R(16) TH_R(24)
    x0 += ks2; x1 += k0 + 2u;
    TH_R(13) TH_R(15) TH_R(26) TH_R(6)
    x0 += k0;  x1 += k1 + 3u;
    TH_R(17) TH_R(29) TH_R(16) TH_R(24)
    x0 += k1;  x1 += ks2 + 4u;
    TH_R(13) TH_R(15) TH_R(26) TH_R(6)
    x0 += ks2; x1 += k0 + 5u;
#undef TH_R
    o0 = x0; o1 = x1;
}
static inline float h_unit_float(unsigned bits) {
    union { unsigned u; float f; } c;
    c.u = (bits >> 9) | 0x3f800000u;
    return c.f - 1.0f;
}

// ---------------------------------------------------------------------------
// bf16 3-term split-compensated NT GEMM (mma.m16n8k16).
// C[m,n] = scale*sum_k A[m,k]*B[n,k] (+bias); fp32 in/out, K = 512.
// Each float x = hi + lo (hi = RN bf16, lo = RN bf16 of residual); compute
// hh + hl + lh in fp32 accumulators (ll + residuals ~2^-17, sign-symmetric).
// 128x128 tile, BK=16 (32 slabs), 128 threads (4 warps, 64x64 warp tile),
// 2 CTA/SM.  smem: 4 planes (Ah/Al/Bh/Bl) x 4KB, double-buffered = 32KB.
// OUT_T (projections): grid.z selects Q vs K, output stored transposed.
// !OUT_T (am0): grid.z = batch.
// ---------------------------------------------------------------------------
__device__ __forceinline__ void mma_bf16(float c[4], const uint32_t a[4],
                                         uint32_t b0, uint32_t b1) {
    asm volatile(
        "mma.sync.aligned.m16n8k16.row.col.f32.bf16.bf16.f32 "
        "{%0,%1,%2,%3}, {%4,%5,%6,%7}, {%8,%9}, {%0,%1,%2,%3};\n"
        : "+f"(c[0]), "+f"(c[1]), "+f"(c[2]), "+f"(c[3])
        : "r"(a[0]), "r"(a[1]), "r"(a[2]), "r"(a[3]), "r"(b0), "r"(b1));
}
__device__ __forceinline__ void ldsm4(uint32_t r[4], uint32_t saddr) {
    asm volatile("ldmatrix.sync.aligned.m8n8.x4.shared.b16 {%0,%1,%2,%3}, [%4];"
                 : "=r"(r[0]), "=r"(r[1]), "=r"(r[2]), "=r"(r[3]) : "r"(saddr));
}
// pack two floats to bf16x2 (RN), x in low half
__device__ __forceinline__ uint32_t cvt2bf(float x, float y) {
    uint32_t r;
    asm("cvt.rn.bf16x2.f32 %0, %1, %2;" : "=r"(r) : "f"(y), "f"(x));
    return r;
}
__device__ __forceinline__ float bf_lo_f(uint32_t p) {       // low bf16 -> f32
    return __uint_as_float(p << 16);
}
__device__ __forceinline__ float bf_hi_f(uint32_t p) {       // high bf16 -> f32
    return __uint_as_float(p & 0xFFFF0000u);
}
// byte offset of 16B granule g (g=0: k0-7, g=1: k8-15) of row r; 32B rows,
// XOR swizzle on granule vs row bit2 -> conflict-free LDSM/STS.
__device__ __forceinline__ int swb(int r, int g) {
    return r * 32 + ((g ^ ((r >> 2) & 1)) << 4);
}

#define PLANE 4096
#define BUFSZ 16384

template <bool OUT_T>
__global__ __launch_bounds__(128, 2)
void gemm_bf3(const float* __restrict__ A0, const float* __restrict__ A1,
              const float* __restrict__ W0, const float* __restrict__ W1,
              const float* __restrict__ bias0, const float* __restrict__ bias1,
              float* __restrict__ C0, float* __restrict__ C1, float scale) {
    __shared__ __align__(16) char smemRaw[2 * BUFSZ];
    const int t = threadIdx.x;

    const float* A;
    const float* B;
    const float* bias;
    float* C;
    if (OUT_T) {
        const int sel = blockIdx.z;
        A = sel ? A1 : A0;
        B = sel ? W1 : W0;
        bias = sel ? bias1 : bias0;
        C = sel ? C1 : C0;
    } else {
        const int z = blockIdx.z;
        A = A0 + (size_t)z * (kA * kA);
        B = W0 + (size_t)z * (kA * kA);
        bias = nullptr;
        C = C0 + (size_t)z * (kA * kA);
    }
    const int n0 = blockIdx.x * 128;
    const int m0 = blockIdx.y * 128;

    const int lane = t & 31, wid = t >> 5;
    const int wm = (wid >> 1) * 64, wn = (wid & 1) * 64;
    const int gid = lane >> 2, tig = lane & 3;

    const float* Aptr = A + (size_t)(m0 + t) * 512;
    const float* Bptr = B + (size_t)(n0 + t) * 512;
    const int off0 = swb(t, 0), off1 = swb(t, 1);

    // ldsm lane mapping: groups of 8 lanes -> (row-lo g0, row-hi g0, row-lo g1, row-hi g1)
    const int row_l = ((lane >> 3) & 1) * 8 + (lane & 7);
    const int gsel = (lane >> 4) & 1;
    int aOff[4], bOff[4];
#pragma unroll
    for (int mi = 0; mi < 4; mi++) aOff[mi] = swb(wm + mi * 16 + row_l, gsel);
#pragma unroll
    for (int p = 0; p < 4; p++)    bOff[p]  = swb(wn + p * 16 + row_l, gsel);

    const uint32_t sbase = (uint32_t)__cvta_generic_to_shared(smemRaw);

    float c[4][8][4];
#pragma unroll
    for (int mi = 0; mi < 4; mi++)
#pragma unroll
        for (int ni = 0; ni < 8; ni++)
#pragma unroll
            for (int r = 0; r < 4; r++) c[mi][ni][r] = 0.f;

    float4 ra[4], rb[4];
    auto gload = [&](int kc) {
#pragma unroll
        for (int q = 0; q < 4; q++) {
            ra[q] = *reinterpret_cast<const float4*>(Aptr + kc * 16 + q * 4);
            rb[q] = *reinterpret_cast<const float4*>(Bptr + kc * 16 + q * 4);
        }
    };
    // split+pack one 8-float granule into hi/lo 16B each
    auto packg = [&](const float4 &f0, const float4 &f1, uint4 &hi, uint4 &lo) {
        hi.x = cvt2bf(f0.x, f0.y);
        hi.y = cvt2bf(f0.z, f0.w);
        hi.z = cvt2bf(f1.x, f1.y);
        hi.w = cvt2bf(f1.z, f1.w);
        lo.x = cvt2bf(f0.x - bf_lo_f(hi.x), f0.y - bf_hi_f(hi.x));
        lo.y = cvt2bf(f0.z - bf_lo_f(hi.y), f0.w - bf_hi_f(hi.y));
        lo.z = cvt2bf(f1.x - bf_lo_f(hi.z), f1.y - bf_hi_f(hi.z));
        lo.w = cvt2bf(f1.z - bf_lo_f(hi.w), f1.w - bf_hi_f(hi.w));
    };
    auto sts = [&](int buf) {
        char* base = smemRaw + buf * BUFSZ;
        uint4 hi, lo;
        packg(ra[0], ra[1], hi, lo);     // A, k0-7
        *reinterpret_cast<uint4*>(base + off0) = hi;
        *reinterpret_cast<uint4*>(base + PLANE + off0) = lo;
        packg(ra[2], ra[3], hi, lo);     // A, k8-15
        *reinterpret_cast<uint4*>(base + off1) = hi;
        *reinterpret_cast<uint4*>(base + PLANE + off1) = lo;
        packg(rb[0], rb[1], hi, lo);     // B, k0-7
        *reinterpret_cast<uint4*>(base + 2 * PLANE + off0) = hi;
        *reinterpret_cast<uint4*>(base + 3 * PLANE + off0) = lo;
        packg(rb[2], rb[3], hi, lo);     // B, k8-15
        *reinterpret_cast<uint4*>(base + 2 * PLANE + off1) = hi;
        *reinterpret_cast<uint4*>(base + 3 * PLANE + off1) = lo;
    };

    gload(0);
    sts(0);
    __syncthreads();

    for (int ks = 0; ks < 32; ks++) {
        const int buf = ks & 1;
        const uint32_t bo = sbase + (uint32_t)buf * BUFSZ;
        if (ks < 31) gload(ks + 1);

        uint32_t ah[4][4], al[4][4], bh[4][4], bl[4][4];
#pragma unroll
        for (int mi = 0; mi < 4; mi++) ldsm4(ah[mi], bo + aOff[mi]);
#pragma unroll
        for (int mi = 0; mi < 4; mi++) ldsm4(al[mi], bo + PLANE + aOff[mi]);
#pragma unroll
        for (int p = 0; p < 4; p++) ldsm4(bh[p], bo + 2 * PLANE + bOff[p]);
#pragma unroll
        for (int p = 0; p < 4; p++) ldsm4(bl[p], bo + 3 * PLANE + bOff[p]);

#pragma unroll
        for (int mi = 0; mi < 4; mi++)
#pragma unroll
            for (int ni = 0; ni < 8; ni++) {
                const int p = ni >> 1, s = ni & 1;
                // frag pairing: regs (s, s+2) = (k-lo, k-hi) for this n-octet
                mma_bf16(c[mi][ni], ah[mi], bh[p][s], bh[p][s + 2]);
                mma_bf16(c[mi][ni], ah[mi], bl[p][s], bl[p][s + 2]);
                mma_bf16(c[mi][ni], al[mi], bh[p][s], bh[p][s + 2]);
            }
        if (ks < 31) {
            sts(buf ^ 1);
            __syncthreads();
        }
    }

#pragma unroll
    for (int mi = 0; mi < 4; mi++) {
#pragma unroll
        for (int ni = 0; ni < 8; ni++) {
            const int gm = m0 + wm + mi * 16 + gid;
            const int gc = n0 + wn + ni * 8 + 2 * tig;
            if (OUT_T) {
                const float bv0 = bias[gc], bv1 = bias[gc + 1];
                float* Cb = C + (size_t)(gm >> 9) * (kA * kA);
                const int j0 = gm & 511, j1 = (gm + 8) & 511;
                Cb[(size_t)gc * 512 + j0]       = c[mi][ni][0] + bv0;
                Cb[(size_t)(gc + 1) * 512 + j0] = c[mi][ni][1] + bv1;
                Cb[(size_t)gc * 512 + j1]       = c[mi][ni][2] + bv0;
                Cb[(size_t)(gc + 1) * 512 + j1] = c[mi][ni][3] + bv1;
            } else {
                float2 o0, o1;
                o0.x = c[mi][ni][0] * scale; o0.y = c[mi][ni][1] * scale;
                o1.x = c[mi][ni][2] * scale; o1.y = c[mi][ni][3] * scale;
                *reinterpret_cast<float2*>(&C[(size_t)gm * 512 + gc]) = o0;
                *reinterpret_cast<float2*>(&C[(size_t)(gm + 8) * 512 + gc]) = o1;
            }
        }
    }
}

// ---------------------------------------------------------------------------
// Vp[b,i] = sum_k V[b,k]*Wv[i,k] + bv[i].  Block per i, warp w -> b=w,w+8.
// ---------------------------------------------------------------------------
__global__ __launch_bounds__(256)
void vp_kernel(const float* __restrict__ V, const float* __restrict__ Wv,
               const float* __restrict__ bv) {
    const int i = blockIdx.x;
    const int w = threadIdx.x >> 5, lane = threadIdx.x & 31;
    const float* wr = Wv + (size_t)i * 512;
    float a0 = 0.f, a1 = 0.f;
#pragma unroll
    for (int cc = 0; cc < 4; cc++) {
        const int k = cc * 128 + lane * 4;
        float4 w4 = *reinterpret_cast<const float4*>(wr + k);
        float4 v0 = *reinterpret_cast<const float4*>(V + w * 512 + k);
        float4 v1 = *reinterpret_cast<const float4*>(V + (w + 8) * 512 + k);
        a0 += w4.x * v0.x + w4.y * v0.y + w4.z * v0.z + w4.w * v0.w;
        a1 += w4.x * v1.x + w4.y * v1.y + w4.z * v1.z + w4.w * v1.w;
    }
    a0 = warpSum(a0); a1 = warpSum(a1);
    if (lane == 0) {
        float b = bv[i];
        g_Vp[w * 512 + i] = a0 + b;
        g_Vp[(w + 8) * 512 + i] = a1 + b;
    }
}

// ---------------------------------------------------------------------------
// Fused kernels — mutate / crossover chosen at capture time on host.
// ---------------------------------------------------------------------------
__global__ __launch_bounds__(256)
void fused_mut(unsigned km0, unsigned km1) {
    const int i = blockIdx.x, b = blockIdx.y;
    const int t = threadIdx.x, lane = t & 31, h = t >> 5;
    __shared__ float sv[512], svp[512];

    if (t < 128)
        *reinterpret_cast<float4*>(&sv[t * 4]) =
            *reinterpret_cast<const float4*>(g_am0 + ((size_t)b * kA + i) * kA + t * 4);
    else
        *reinterpret_cast<float4*>(&svp[(t - 128) * 4]) =
            *reinterpret_cast<const float4*>(g_Vp + b * kA + (t - 128) * 4);
    __syncthreads();

    const unsigned base = ((unsigned)(b * 8 + h) << 18) + ((unsigned)i << 9) + (unsigned)lane;
    float s = 0.f, d = 0.f;
#pragma unroll 8
    for (int cc = 0; cc < 16; cc++) {
        const int j = cc * 32 + lane;
        unsigned o0, o1;
        tf2x32(km0, km1, 0u, base + (unsigned)(cc * 32), o0, o1);
        const float e = __expf(sv[j] * mut_factor(o0 ^ o1));
        s += e; d += e * svp[j];
    }
    s = warpSum(s); d = warpSum(d);
    if (lane == 0) g_out3[(b * 8 + h) * kA + i] = d / s;
}

struct CrossArgs { int r1[kB * kH]; int r2[kB * kH]; };

__global__ __launch_bounds__(256)
void fused_cross(CrossArgs args) {
    const int i = blockIdx.x, b = blockIdx.y;
    const int t = threadIdx.x, lane = t & 31, h = t >> 5;
    __shared__ float sv[512], svp[512];

    if (t < 128)
        *reinterpret_cast<float4*>(&sv[t * 4]) =
            *reinterpret_cast<const float4*>(g_am0 + ((size_t)b * kA + i) * kA + t * 4);
    else
        *reinterpret_cast<float4*>(&svp[(t - 128) * 4]) =
            *reinterpret_cast<const float4*>(g_Vp + b * kA + (t - 128) * 4);
    __syncthreads();

    const int bh = b * 8 + h;
    const int r1 = args.r1[bh], r2 = args.r2[bh];
    const int src = (i == r1) ? r2 : (i == r2) ? r1 : i;
    const float* srow = g_am0 + ((size_t)b * kA + src) * kA;
    float s = 0.f, d = 0.f;
#pragma unroll 4
    for (int cc = 0; cc < 16; cc++) {
        const int j = cc * 32 + lane;
        const float v = (src == i || j < kC) ? sv[j] : srow[j];
        const float e = __expf(v);
        s += e; d += e * svp[j];
    }
    s = warpSum(s); d = warpSum(d);
    if (lane == 0) g_out3[bh * kA + i] = d / s;
}

// ---------------------------------------------------------------------------
// y[b,o] = sum_x g_out3[b*4096+x]*WOw[o,x] + WOb[o].
// ---------------------------------------------------------------------------
__global__ __launch_bounds__(256)
void out_proj(const float* __restrict__ WOw, const float* __restrict__ WOb,
              float* __restrict__ y) {
    __shared__ float xs[16][516];
    const int t = threadIdx.x;
    const int o_l = t >> 4, bq = t & 15;
    const int o = blockIdx.x * 16 + o_l;
    float acc = 0.f;

    for (int ch = 0; ch < 8; ch++) {
#pragma unroll
        for (int l = 0; l < 8; l++) {
            int idx = t + l * 256;
            int row = idx >> 7, c4 = idx & 127;
            *reinterpret_cast<float4*>(&xs[row][c4 * 4]) =
                *reinterpret_cast<const float4*>(g_out3 + row * 4096 + ch * 512 + c4 * 4);
        }
        __syncthreads();
        const float4* Wp = reinterpret_cast<const float4*>(WOw + (size_t)o * 4096 + ch * 512);
#pragma unroll 8
        for (int k4 = 0; k4 < 128; k4++) {
            float4 w4 = Wp[k4];
            float4 x4 = *reinterpret_cast<const float4*>(&xs[bq][k4 * 4]);
            acc += w4.x * x4.x + w4.y * x4.y + w4.z * x4.z + w4.w * x4.w;
        }
        __syncthreads();
    }
    y[bq * 512 + o] = acc + WOb[o];
}

// ---------------------------------------------------------------------------
// Launch — host PRNG; bf16 3-term GEMMs; simple overlap (vp on s1):
//   s0: proj -> am0(full) -> (wait vp) fused -> out_proj
//   s1: vp
// ---------------------------------------------------------------------------
extern "C" void kernel_launch(void* const* d_in, const int* in_sizes, int n_in,
                              void* d_out, int out_size) {
    const float* Q   = (const float*)d_in[0];
    const float* K   = (const float*)d_in[1];
    const float* V   = (const float*)d_in[2];
    const float* WQw = (const float*)d_in[3];
    const float* WQb = (const float*)d_in[4];
    const float* WKw = (const float*)d_in[5];
    const float* WKb = (const float*)d_in[6];
    const float* WVw = (const float*)d_in[7];
    const float* WVb = (const float*)d_in[8];
    const float* WOw = (const float*)d_in[9];
    const float* WOb = (const float*)d_in[10];
    float* y = (float*)d_out;

    float* dQpT; cudaGetSymbolAddress((void**)&dQpT, g_QpT);
    float* dKpT; cudaGetSymbolAddress((void**)&dKpT, g_KpT);
    float* dam;  cudaGetSymbolAddress((void**)&dam,  g_am0);

    static cudaStream_t s1 = nullptr;
    static cudaEvent_t evFork, evV;
    if (s1 == nullptr) {
        cudaStreamCreateWithFlags(&s1, cudaStreamNonBlocking);
        cudaEventCreateWithFlags(&evFork, cudaEventDisableTiming);
        cudaEventCreateWithFlags(&evV,    cudaEventDisableTiming);
    }

    // --- host PRNG (deterministic, key = 42) ---
    unsigned kp0, kp1, km0, km1, kr10, kr11, kr20, kr21;
    h_tf2x32(0u, 42u, 0u, 0u, kp0, kp1);
    h_tf2x32(0u, 42u, 0u, 1u, km0, km1);
    h_tf2x32(0u, 42u, 0u, 2u, kr10, kr11);
    h_tf2x32(0u, 42u, 0u, 3u, kr20, kr21);
    unsigned o0, o1;
    h_tf2x32(kp0, kp1, 0u, 0u, o0, o1);
    const bool mutate = (h_unit_float(o0 ^ o1) <= 0.6f);
    CrossArgs ca;
    if (!mutate) {
        unsigned a0, a1;
        h_tf2x32(kr10, kr11, 0u, 1u, a0, a1);
        for (int t = 0; t < kB * kH; t++) {
            h_tf2x32(a0, a1, 0u, (unsigned)t, o0, o1);
            ca.r1[t] = (int)((o0 ^ o1) & 511u);
        }
        h_tf2x32(kr20, kr21, 0u, 1u, a0, a1);
        for (int t = 0; t < kB * kH; t++) {
            h_tf2x32(a0, a1, 0u, (unsigned)t, o0, o1);
            ca.r2[t] = (int)((o0 ^ o1) & 511u);
        }
    }

    // fork s1; vp overlaps the projection GEMM
    cudaEventRecord(evFork, 0);
    cudaStreamWaitEvent(s1, evFork, 0);
    vp_kernel<<<512, 256, 0, s1>>>(V, WVw, WVb);
    cudaEventRecord(evV, s1);

    // s0: merged Q/K projections (bf16 3-term)
    gemm_bf3<true><<<dim3(4, 64, 2), 128>>>(Q, K, WQw, WKw, WQb, WKb,
                                            dQpT, dKpT, 1.0f);
    // s0: am0, full grid (256 CTAs)
    gemm_bf3<false><<<dim3(4, 4, 16), 128>>>(dQpT, nullptr, dKpT, nullptr,
                                             nullptr, nullptr, dam, nullptr,
                                             1.0f / sqrtf(8.0f));
    // join vp, then fused + out_proj on s0
    cudaStreamWaitEvent(0, evV, 0);
    if (mutate)
        fused_mut<<<dim3(512, 16), 256>>>(km0, km1);
    else
        fused_cross<<<dim3(512, 16), 256>>>(ca);
    out_proj<<<32, 256>>>(WOw, WOb, y);
}

// round 17
// speedup vs baseline: 1.2055x; 1.1205x over previous
#include <cuda_runtime.h>
#include <cuda_bf16.h>
#include <cstdint>

#define kB 16
#define kH 8
#define kA 512
#define kC 359   /* A - int(A*0.3) */

// ---------------------------------------------------------------------------
// Scratch (device globals)
// ---------------------------------------------------------------------------
__device__ float g_QpT[kB * kA * kA];      // (B, A, A)  QpT[b,i,j] (j contiguous)
__device__ float g_KpT[kB * kA * kA];      // (B, A, A)  KpT[b,n,j]
__device__ float g_am0[kB * kA * kA];      // (B, A, A)  am0[b,i,n] (scaled)
__device__ float g_Vp[kB * kA];
__device__ float g_out3[kB * kH * kA];     // [bh*512 + i]

// ---------------------------------------------------------------------------
// Threefry2x32 — device (mutation factors) + host (keys)
// ---------------------------------------------------------------------------
__device__ __forceinline__ void tf2x32(unsigned k0, unsigned k1,
                                       unsigned x0, unsigned x1,
                                       unsigned &o0, unsigned &o1) {
    unsigned ks2 = k0 ^ k1 ^ 0x1BD11BDAu;
    x0 += k0; x1 += k1;
#define TF_R(r) { x0 += x1; x1 = __funnelshift_l(x1, x1, r); x1 ^= x0; }
    TF_R(13) TF_R(15) TF_R(26) TF_R(6)
    x0 += k1;  x1 += ks2 + 1u;
    TF_R(17) TF_R(29) TF_R(16) TF_R(24)
    x0 += ks2; x1 += k0 + 2u;
    TF_R(13) TF_R(15) TF_R(26) TF_R(6)
    x0 += k0;  x1 += k1 + 3u;
    TF_R(17) TF_R(29) TF_R(16) TF_R(24)
    x0 += k1;  x1 += ks2 + 4u;
    TF_R(13) TF_R(15) TF_R(26) TF_R(6)
    x0 += ks2; x1 += k0 + 5u;
#undef TF_R
    o0 = x0; o1 = x1;
}
__device__ __forceinline__ float unit_float(unsigned bits) {
    return __uint_as_float((bits >> 9) | 0x3f800000u) - 1.0f;
}
__device__ __forceinline__ float mut_factor(unsigned bits) {
    const float mn = 0.7f, mx = 1.3f;
    return fmaxf(mn, unit_float(bits) * (mx - mn) + mn);
}
__device__ __forceinline__ float warpSum(float v) {
#pragma unroll
    for (int o = 16; o > 0; o >>= 1) v += __shfl_xor_sync(0xffffffffu, v, o);
    return v;
}

static inline unsigned h_rotl(unsigned v, int r) { return (v << r) | (v >> (32 - r)); }
static void h_tf2x32(unsigned k0, unsigned k1, unsigned x0, unsigned x1,
                     unsigned &o0, unsigned &o1) {
    unsigned ks2 = k0 ^ k1 ^ 0x1BD11BDAu;
    x0 += k0; x1 += k1;
#define TH_R(r) { x0 += x1; x1 = h_rotl(x1, r); x1 ^= x0; }
    TH_R(13) TH_R(15) TH_R(26) TH_R(6)
    x0 += k1;  x1 += ks2 + 1u;
    TH_R(17) TH_R(29) TH_R(16) TH_R(24)
    x0 += ks2; x1 += k0 + 2u;
    TH_R(13) TH_R(15) TH_R(26) TH_R(6)
    x0 += k0;  x1 += k1 + 3u;
    TH_R(17) TH_R(29) TH_R(16) TH_R(24)
    x0 += k1;  x1 += ks2 + 4u;
    TH_R(13) TH_R(15) TH_R(26) TH_R(6)
    x0 += ks2; x1 += k0 + 5u;
#undef TH_R
    o0 = x0; o1 = x1;
}
static inline float h_unit_float(unsigned bits) {
    union { unsigned u; float f; } c;
    c.u = (bits >> 9) | 0x3f800000u;
    return c.f - 1.0f;
}

// ---------------------------------------------------------------------------
// bf16 3-term split-compensated NT GEMM (mma.m16n8k16), 256 threads.
// C[m,n] = scale*sum_k A[m,k]*B[n,k] (+bias); fp32 in/out, K = 512.
// x = hi + lo (RN bf16 each); accumulate hh + hl + lh in fp32.
// 128x128 tile, BK=16 (32 slabs), 8 warps (warp tile 64x32), 2 CTA/SM
// -> 16 warps/SM = 4 warps/SMSP (latency hiding; R14 proved the mainloop
// is latency-exposed, not tensor-bound).
// smem: 4 planes (Ah/Al/Bh/Bl) x 4KB, double-buffered = 32KB.
// OUT_T (projections): grid.z selects Q vs K, output stored transposed.
// !OUT_T (am0): grid.z = batch.
// ---------------------------------------------------------------------------
__device__ __forceinline__ void mma_bf16(float c[4], const uint32_t a[4],
                                         uint32_t b0, uint32_t b1) {
    asm volatile(
        "mma.sync.aligned.m16n8k16.row.col.f32.bf16.bf16.f32 "
        "{%0,%1,%2,%3}, {%4,%5,%6,%7}, {%8,%9}, {%0,%1,%2,%3};\n"
        : "+f"(c[0]), "+f"(c[1]), "+f"(c[2]), "+f"(c[3])
        : "r"(a[0]), "r"(a[1]), "r"(a[2]), "r"(a[3]), "r"(b0), "r"(b1));
}
__device__ __forceinline__ void ldsm4(uint32_t r[4], uint32_t saddr) {
    asm volatile("ldmatrix.sync.aligned.m8n8.x4.shared.b16 {%0,%1,%2,%3}, [%4];"
                 : "=r"(r[0]), "=r"(r[1]), "=r"(r[2]), "=r"(r[3]) : "r"(saddr));
}
__device__ __forceinline__ uint32_t cvt2bf(float x, float y) {
    uint32_t r;
    asm("cvt.rn.bf16x2.f32 %0, %1, %2;" : "=r"(r) : "f"(y), "f"(x));
    return r;
}
__device__ __forceinline__ float bf_lo_f(uint32_t p) {
    return __uint_as_float(p << 16);
}
__device__ __forceinline__ float bf_hi_f(uint32_t p) {
    return __uint_as_float(p & 0xFFFF0000u);
}
// byte offset of 16B granule g of row r; 32B rows, XOR swizzle (granule vs
// row bit2) -> conflict-free LDSM/STS.
__device__ __forceinline__ int swb(int r, int g) {
    return r * 32 + ((g ^ ((r >> 2) & 1)) << 4);
}

#define PLANE 4096
#define BUFSZ 16384

template <bool OUT_T>
__global__ __launch_bounds__(256, 2)
void gemm_bf3(const float* __restrict__ A0, const float* __restrict__ A1,
              const float* __restrict__ W0, const float* __restrict__ W1,
              const float* __restrict__ bias0, const float* __restrict__ bias1,
              float* __restrict__ C0, float* __restrict__ C1, float scale) {
    __shared__ __align__(16) char smemRaw[2 * BUFSZ];
    const int t = threadIdx.x;

    const float* A;
    const float* B;
    const float* bias;
    float* C;
    if (OUT_T) {
        const int sel = blockIdx.z;
        A = sel ? A1 : A0;
        B = sel ? W1 : W0;
        bias = sel ? bias1 : bias0;
        C = sel ? C1 : C0;
    } else {
        const int z = blockIdx.z;
        A = A0 + (size_t)z * (kA * kA);
        B = W0 + (size_t)z * (kA * kA);
        bias = nullptr;
        C = C0 + (size_t)z * (kA * kA);
    }
    const int n0 = blockIdx.x * 128;
    const int m0 = blockIdx.y * 128;

    const int lane = t & 31, wid = t >> 5;
    const int wm = (wid >> 2) * 64;          // 0 or 64
    const int wn = (wid & 3) * 32;           // 0,32,64,96
    const int gid = lane >> 2, tig = lane & 3;

    // loader: thread t owns (row t>>1, granule t&1) of both tiles
    const int lrow = t >> 1, lg = t & 1;
    const float* Aptr = A + (size_t)(m0 + lrow) * 512 + lg * 8;
    const float* Bptr = B + (size_t)(n0 + lrow) * 512 + lg * 8;
    const int loff = swb(lrow, lg);

    // ldsm lane mapping
    const int row_l = ((lane >> 3) & 1) * 8 + (lane & 7);
    const int gsel = (lane >> 4) & 1;
    int aOff[4], bOff[2];
#pragma unroll
    for (int mi = 0; mi < 4; mi++) aOff[mi] = swb(wm + mi * 16 + row_l, gsel);
#pragma unroll
    for (int p = 0; p < 2; p++)    bOff[p]  = swb(wn + p * 16 + row_l, gsel);

    const uint32_t sbase = (uint32_t)__cvta_generic_to_shared(smemRaw);

    float c[4][4][4];
#pragma unroll
    for (int mi = 0; mi < 4; mi++)
#pragma unroll
        for (int ni = 0; ni < 4; ni++)
#pragma unroll
            for (int r = 0; r < 4; r++) c[mi][ni][r] = 0.f;

    float4 ra0, ra1, rb0, rb1;
    auto gload = [&](int kc) {
        ra0 = *reinterpret_cast<const float4*>(Aptr + kc * 16);
        ra1 = *reinterpret_cast<const float4*>(Aptr + kc * 16 + 4);
        rb0 = *reinterpret_cast<const float4*>(Bptr + kc * 16);
        rb1 = *reinterpret_cast<const float4*>(Bptr + kc * 16 + 4);
    };
    auto packg = [&](const float4 &f0, const float4 &f1, uint4 &hi, uint4 &lo) {
        hi.x = cvt2bf(f0.x, f0.y);
        hi.y = cvt2bf(f0.z, f0.w);
        hi.z = cvt2bf(f1.x, f1.y);
        hi.w = cvt2bf(f1.z, f1.w);
        lo.x = cvt2bf(f0.x - bf_lo_f(hi.x), f0.y - bf_hi_f(hi.x));
        lo.y = cvt2bf(f0.z - bf_lo_f(hi.y), f0.w - bf_hi_f(hi.y));
        lo.z = cvt2bf(f1.x - bf_lo_f(hi.z), f1.y - bf_hi_f(hi.z));
        lo.w = cvt2bf(f1.z - bf_lo_f(hi.w), f1.w - bf_hi_f(hi.w));
    };
    auto sts = [&](int buf) {
        char* base = smemRaw + buf * BUFSZ;
        uint4 hi, lo;
        packg(ra0, ra1, hi, lo);
        *reinterpret_cast<uint4*>(base + loff) = hi;
        *reinterpret_cast<uint4*>(base + PLANE + loff) = lo;
        packg(rb0, rb1, hi, lo);
        *reinterpret_cast<uint4*>(base + 2 * PLANE + loff) = hi;
        *reinterpret_cast<uint4*>(base + 3 * PLANE + loff) = lo;
    };

    gload(0);
    sts(0);
    __syncthreads();

    for (int ks = 0; ks < 32; ks++) {
        const int buf = ks & 1;
        const uint32_t bo = sbase + (uint32_t)buf * BUFSZ;
        if (ks < 31) gload(ks + 1);

        uint32_t ah[4][4], al[4][4], bh[2][4], bl[2][4];
#pragma unroll
        for (int mi = 0; mi < 4; mi++) ldsm4(ah[mi], bo + aOff[mi]);
#pragma unroll
        for (int mi = 0; mi < 4; mi++) ldsm4(al[mi], bo + PLANE + aOff[mi]);
#pragma unroll
        for (int p = 0; p < 2; p++) ldsm4(bh[p], bo + 2 * PLANE + bOff[p]);
#pragma unroll
        for (int p = 0; p < 2; p++) ldsm4(bl[p], bo + 3 * PLANE + bOff[p]);

#pragma unroll
        for (int mi = 0; mi < 4; mi++)
#pragma unroll
            for (int ni = 0; ni < 4; ni++) {
                const int p = ni >> 1, s = ni & 1;
                mma_bf16(c[mi][ni], ah[mi], bh[p][s], bh[p][s + 2]);
                mma_bf16(c[mi][ni], ah[mi], bl[p][s], bl[p][s + 2]);
                mma_bf16(c[mi][ni], al[mi], bh[p][s], bh[p][s + 2]);
            }
        if (ks < 31) {
            sts(buf ^ 1);
            __syncthreads();
        }
    }

#pragma unroll
    for (int mi = 0; mi < 4; mi++) {
#pragma unroll
        for (int ni = 0; ni < 4; ni++) {
            const int gm = m0 + wm + mi * 16 + gid;
            const int gc = n0 + wn + ni * 8 + 2 * tig;
            if (OUT_T) {
                const float bv0 = bias[gc], bv1 = bias[gc + 1];
                float* Cb = C + (size_t)(gm >> 9) * (kA * kA);
                const int j0 = gm & 511, j1 = (gm + 8) & 511;
                Cb[(size_t)gc * 512 + j0]       = c[mi][ni][0] + bv0;
                Cb[(size_t)(gc + 1) * 512 + j0] = c[mi][ni][1] + bv1;
                Cb[(size_t)gc * 512 + j1]       = c[mi][ni][2] + bv0;
                Cb[(size_t)(gc + 1) * 512 + j1] = c[mi][ni][3] + bv1;
            } else {
                float2 o0, o1;
                o0.x = c[mi][ni][0] * scale; o0.y = c[mi][ni][1] * scale;
                o1.x = c[mi][ni][2] * scale; o1.y = c[mi][ni][3] * scale;
                *reinterpret_cast<float2*>(&C[(size_t)gm * 512 + gc]) = o0;
                *reinterpret_cast<float2*>(&C[(size_t)(gm + 8) * 512 + gc]) = o1;
            }
        }
    }
}

// ---------------------------------------------------------------------------
// Vp[b,i] = sum_k V[b,k]*Wv[i,k] + bv[i].  Block per i, warp w -> b=w,w+8.
// ---------------------------------------------------------------------------
__global__ __launch_bounds__(256)
void vp_kernel(const float* __restrict__ V, const float* __restrict__ Wv,
               const float* __restrict__ bv) {
    const int i = blockIdx.x;
    const int w = threadIdx.x >> 5, lane = threadIdx.x & 31;
    const float* wr = Wv + (size_t)i * 512;
    float a0 = 0.f, a1 = 0.f;
#pragma unroll
    for (int cc = 0; cc < 4; cc++) {
        const int k = cc * 128 + lane * 4;
        float4 w4 = *reinterpret_cast<const float4*>(wr + k);
        float4 v0 = *reinterpret_cast<const float4*>(V + w * 512 + k);
        float4 v1 = *reinterpret_cast<const float4*>(V + (w + 8) * 512 + k);
        a0 += w4.x * v0.x + w4.y * v0.y + w4.z * v0.z + w4.w * v0.w;
        a1 += w4.x * v1.x + w4.y * v1.y + w4.z * v1.z + w4.w * v1.w;
    }
    a0 = warpSum(a0); a1 = warpSum(a1);
    if (lane == 0) {
        float b = bv[i];
        g_Vp[w * 512 + i] = a0 + b;
        g_Vp[(w + 8) * 512 + i] = a1 + b;
    }
}

// ---------------------------------------------------------------------------
// Fused kernels — mutate / crossover chosen at capture time on host.
// ---------------------------------------------------------------------------
__global__ __launch_bounds__(256)
void fused_mut(unsigned km0, unsigned km1) {
    const int i = blockIdx.x, b = blockIdx.y;
    const int t = threadIdx.x, lane = t & 31, h = t >> 5;
    __shared__ float sv[512], svp[512];

    if (t < 128)
        *reinterpret_cast<float4*>(&sv[t * 4]) =
            *reinterpret_cast<const float4*>(g_am0 + ((size_t)b * kA + i) * kA + t * 4);
    else
        *reinterpret_cast<float4*>(&svp[(t - 128) * 4]) =
            *reinterpret_cast<const float4*>(g_Vp + b * kA + (t - 128) * 4);
    __syncthreads();

    const unsigned base = ((unsigned)(b * 8 + h) << 18) + ((unsigned)i << 9) + (unsigned)lane;
    float s = 0.f, d = 0.f;
#pragma unroll 8
    for (int cc = 0; cc < 16; cc++) {
        const int j = cc * 32 + lane;
        unsigned o0, o1;
        tf2x32(km0, km1, 0u, base + (unsigned)(cc * 32), o0, o1);
        const float e = __expf(sv[j] * mut_factor(o0 ^ o1));
        s += e; d += e * svp[j];
    }
    s = warpSum(s); d = warpSum(d);
    if (lane == 0) g_out3[(b * 8 + h) * kA + i] = d / s;
}

struct CrossArgs { int r1[kB * kH]; int r2[kB * kH]; };

__global__ __launch_bounds__(256)
void fused_cross(CrossArgs args) {
    const int i = blockIdx.x, b = blockIdx.y;
    const int t = threadIdx.x, lane = t & 31, h = t >> 5;
    __shared__ float sv[512], svp[512];

    if (t < 128)
        *reinterpret_cast<float4*>(&sv[t * 4]) =
            *reinterpret_cast<const float4*>(g_am0 + ((size_t)b * kA + i) * kA + t * 4);
    else
        *reinterpret_cast<float4*>(&svp[(t - 128) * 4]) =
            *reinterpret_cast<const float4*>(g_Vp + b * kA + (t - 128) * 4);
    __syncthreads();

    const int bh = b * 8 + h;
    const int r1 = args.r1[bh], r2 = args.r2[bh];
    const int src = (i == r1) ? r2 : (i == r2) ? r1 : i;
    const float* srow = g_am0 + ((size_t)b * kA + src) * kA;
    float s = 0.f, d = 0.f;
#pragma unroll 4
    for (int cc = 0; cc < 16; cc++) {
        const int j = cc * 32 + lane;
        const float v = (src == i || j < kC) ? sv[j] : srow[j];
        const float e = __expf(v);
        s += e; d += e * svp[j];
    }
    s = warpSum(s); d = warpSum(d);
    if (lane == 0) g_out3[bh * kA + i] = d / s;
}

// ---------------------------------------------------------------------------
// y[b,o] = sum_x g_out3[b*4096+x]*WOw[o,x] + WOb[o].
// ---------------------------------------------------------------------------
__global__ __launch_bounds__(256)
void out_proj(const float* __restrict__ WOw, const float* __restrict__ WOb,
              float* __restrict__ y) {
    __shared__ float xs[16][516];
    const int t = threadIdx.x;
    const int o_l = t >> 4, bq = t & 15;
    const int o = blockIdx.x * 16 + o_l;
    float acc = 0.f;

    for (int ch = 0; ch < 8; ch++) {
#pragma unroll
        for (int l = 0; l < 8; l++) {
            int idx = t + l * 256;
            int row = idx >> 7, c4 = idx & 127;
            *reinterpret_cast<float4*>(&xs[row][c4 * 4]) =
                *reinterpret_cast<const float4*>(g_out3 + row * 4096 + ch * 512 + c4 * 4);
        }
        __syncthreads();
        const float4* Wp = reinterpret_cast<const float4*>(WOw + (size_t)o * 4096 + ch * 512);
#pragma unroll 8
        for (int k4 = 0; k4 < 128; k4++) {
            float4 w4 = Wp[k4];
            float4 x4 = *reinterpret_cast<const float4*>(&xs[bq][k4 * 4]);
            acc += w4.x * x4.x + w4.y * x4.y + w4.z * x4.z + w4.w * x4.w;
        }
        __syncthreads();
    }
    y[bq * 512 + o] = acc + WOb[o];
}

// ---------------------------------------------------------------------------
// Launch — host PRNG; bf16 3-term GEMMs (256 thr); vp overlapped on s1.
// ---------------------------------------------------------------------------
extern "C" void kernel_launch(void* const* d_in, const int* in_sizes, int n_in,
                              void* d_out, int out_size) {
    const float* Q   = (const float*)d_in[0];
    const float* K   = (const float*)d_in[1];
    const float* V   = (const float*)d_in[2];
    const float* WQw = (const float*)d_in[3];
    const float* WQb = (const float*)d_in[4];
    const float* WKw = (const float*)d_in[5];
    const float* WKb = (const float*)d_in[6];
    const float* WVw = (const float*)d_in[7];
    const float* WVb = (const float*)d_in[8];
    const float* WOw = (const float*)d_in[9];
    const float* WOb = (const float*)d_in[10];
    float* y = (float*)d_out;

    float* dQpT; cudaGetSymbolAddress((void**)&dQpT, g_QpT);
    float* dKpT; cudaGetSymbolAddress((void**)&dKpT, g_KpT);
    float* dam;  cudaGetSymbolAddress((void**)&dam,  g_am0);

    static cudaStream_t s1 = nullptr;
    static cudaEvent_t evFork, evV;
    if (s1 == nullptr) {
        cudaStreamCreateWithFlags(&s1, cudaStreamNonBlocking);
        cudaEventCreateWithFlags(&evFork, cudaEventDisableTiming);
        cudaEventCreateWithFlags(&evV,    cudaEventDisableTiming);
    }

    // --- host PRNG (deterministic, key = 42) ---
    unsigned kp0, kp1, km0, km1, kr10, kr11, kr20, kr21;
    h_tf2x32(0u, 42u, 0u, 0u, kp0, kp1);
    h_tf2x32(0u, 42u, 0u, 1u, km0, km1);
    h_tf2x32(0u, 42u, 0u, 2u, kr10, kr11);
    h_tf2x32(0u, 42u, 0u, 3u, kr20, kr21);
    unsigned o0, o1;
    h_tf2x32(kp0, kp1, 0u, 0u, o0, o1);
    const bool mutate = (h_unit_float(o0 ^ o1) <= 0.6f);
    CrossArgs ca;
    if (!mutate) {
        unsigned a0, a1;
        h_tf2x32(kr10, kr11, 0u, 1u, a0, a1);
        for (int t = 0; t < kB * kH; t++) {
            h_tf2x32(a0, a1, 0u, (unsigned)t, o0, o1);
            ca.r1[t] = (int)((o0 ^ o1) & 511u);
        }
        h_tf2x32(kr20, kr21, 0u, 1u, a0, a1);
        for (int t = 0; t < kB * kH; t++) {
            h_tf2x32(a0, a1, 0u, (unsigned)t, o0, o1);
            ca.r2[t] = (int)((o0 ^ o1) & 511u);
        }
    }

    // fork s1; vp overlaps the projection GEMM
    cudaEventRecord(evFork, 0);
    cudaStreamWaitEvent(s1, evFork, 0);
    vp_kernel<<<512, 256, 0, s1>>>(V, WVw, WVb);
    cudaEventRecord(evV, s1);

    // s0: merged Q/K projections (bf16 3-term, 256 thr)
    gemm_bf3<true><<<dim3(4, 64, 2), 256>>>(Q, K, WQw, WKw, WQb, WKb,
                                            dQpT, dKpT, 1.0f);
    // s0: am0, full grid (256 CTAs)
    gemm_bf3<false><<<dim3(4, 4, 16), 256>>>(dQpT, nullptr, dKpT, nullptr,
                                             nullptr, nullptr, dam, nullptr,
                                             1.0f / sqrtf(8.0f));
    // join vp, then fused + out_proj on s0
    cudaStreamWaitEvent(0, evV, 0);
    if (mutate)
        fused_mut<<<dim3(512, 16), 256>>>(km0, km1);
    else
        fused_cross<<<dim3(512, 16), 256>>>(ca);
    out_proj<<<32, 256>>>(WOw, WOb, y);
}